// round 1
// baseline (speedup 1.0000x reference)
#include <cuda_runtime.h>
#include <cstddef>

#define HIDDEN   128
#define INSZ     64
#define NACT     16
#define BATCH    65536
#define TILE_B   128
#define THREADS  128

#define XS_STRIDE 68    // 64 + 4 pad: conflict-free vec4 LDS
#define H0_STRIDE 132   // 128 + 4 pad

extern __shared__ float smem_buf[];

__device__ __forceinline__ float fsig(float z) {
    return __fdividef(1.0f, 1.0f + __expf(-z));
}
__device__ __forceinline__ float ftanh_(float z) {
    // tanh(z) = 2*sigmoid(2z) - 1  (accurate via __expf, ~1e-6 rel err)
    return 2.0f * fsig(2.0f * z) - 1.0f;
}
__device__ __forceinline__ float dot4(float4 a, float4 b, float acc) {
    acc = fmaf(a.x, b.x, acc);
    acc = fmaf(a.y, b.y, acc);
    acc = fmaf(a.z, b.z, acc);
    acc = fmaf(a.w, b.w, acc);
    return acc;
}

__global__ void __launch_bounds__(THREADS)
lstm_policy_fused(
    const float* __restrict__ x,
    const float* __restrict__ Wih0,
    const float* __restrict__ bih0, const float* __restrict__ bhh0,
    const float* __restrict__ Wih1,
    const float* __restrict__ bih1, const float* __restrict__ bhh1,
    const float* __restrict__ Wp,   const float* __restrict__ bp,
    const float* __restrict__ Wv,   const float* __restrict__ bv,
    float* __restrict__ out)
{
    float* xs  = smem_buf;                       // [TILE_B][XS_STRIDE]
    float* h0s = smem_buf + TILE_B * XS_STRIDE;  // [TILE_B][H0_STRIDE]

    const int tid = threadIdx.x;
    const int r0  = blockIdx.x * TILE_B;

    // ---- stage x tile (coalesced float4 global read) ----
    {
        const float4* xg = (const float4*)x;
        #pragma unroll
        for (int idx = tid; idx < TILE_B * (INSZ / 4); idx += THREADS) {
            int r = idx >> 4;        // row within tile
            int c = idx & 15;        // float4 column
            float4 v = xg[(size_t)(r0 + r) * (INSZ / 4) + c];
            *(float4*)&xs[r * XS_STRIDE + 4 * c] = v;
        }
    }
    __syncthreads();

    const float* xrow = &xs[tid * XS_STRIDE];
    float* hrow = &h0s[tid * H0_STRIDE];

    // ---------------- layer 0 ----------------
    // c=0, h=0  =>  gates = x @ Wih0^T + (bih0 + bhh0); f-gate unused.
    for (int j = 0; j < HIDDEN; ++j) {
        float ai = bih0[j]              + bhh0[j];
        float ag = bih0[2 * HIDDEN + j] + bhh0[2 * HIDDEN + j];
        float ao = bih0[3 * HIDDEN + j] + bhh0[3 * HIDDEN + j];

        const float4* wi = (const float4*)(Wih0 + (size_t)j * INSZ);
        const float4* wg = (const float4*)(Wih0 + (size_t)(2 * HIDDEN + j) * INSZ);
        const float4* wo = (const float4*)(Wih0 + (size_t)(3 * HIDDEN + j) * INSZ);

        #pragma unroll
        for (int k = 0; k < INSZ / 4; ++k) {
            float4 xv = *(const float4*)&xrow[4 * k];
            ai = dot4(xv, wi[k], ai);
            ag = dot4(xv, wg[k], ag);
            ao = dot4(xv, wo[k], ao);
        }

        float ig = fsig(ai);
        float gg = ftanh_(ag);
        float og = fsig(ao);
        float cc = ig * gg;                 // f*c term is zero
        hrow[j]  = og * ftanh_(cc);
    }
    // Each thread reads only the h0 row it wrote -> no __syncthreads needed.

    // ---------------- layer 1 + heads ----------------
    float pol[NACT];
    #pragma unroll
    for (int a = 0; a < NACT; ++a) pol[a] = 0.0f;
    float valacc = 0.0f;

    for (int j = 0; j < HIDDEN; ++j) {
        float ai = bih1[j]              + bhh1[j];
        float ag = bih1[2 * HIDDEN + j] + bhh1[2 * HIDDEN + j];
        float ao = bih1[3 * HIDDEN + j] + bhh1[3 * HIDDEN + j];

        const float4* wi = (const float4*)(Wih1 + (size_t)j * HIDDEN);
        const float4* wg = (const float4*)(Wih1 + (size_t)(2 * HIDDEN + j) * HIDDEN);
        const float4* wo = (const float4*)(Wih1 + (size_t)(3 * HIDDEN + j) * HIDDEN);

        #pragma unroll
        for (int k = 0; k < HIDDEN / 4; ++k) {
            float4 xv = *(const float4*)&hrow[4 * k];
            ai = dot4(xv, wi[k], ai);
            ag = dot4(xv, wg[k], ag);
            ao = dot4(xv, wo[k], ao);
        }

        float ig = fsig(ai);
        float gg = ftanh_(ag);
        float og = fsig(ao);
        float h1 = og * ftanh_(ig * gg);

        // accumulate heads on the fly; h1 never materialized
        #pragma unroll
        for (int a = 0; a < NACT; ++a)
            pol[a] = fmaf(h1, Wp[a * HIDDEN + j], pol[a]);
        valacc = fmaf(h1, Wv[j], valacc);
    }

    // ---- write outputs: [policy (B*16) | value (B)] ----
    const int row = r0 + tid;
    float4* po = (float4*)(out + (size_t)row * NACT);
    #pragma unroll
    for (int a4 = 0; a4 < 4; ++a4) {
        float4 v;
        v.x = pol[4 * a4 + 0] + bp[4 * a4 + 0];
        v.y = pol[4 * a4 + 1] + bp[4 * a4 + 1];
        v.z = pol[4 * a4 + 2] + bp[4 * a4 + 2];
        v.w = pol[4 * a4 + 3] + bp[4 * a4 + 3];
        po[a4] = v;
    }
    out[(size_t)BATCH * NACT + row] = valacc + bv[0];
}

extern "C" void kernel_launch(void* const* d_in, const int* in_sizes, int n_in,
                              void* d_out, int out_size)
{
    (void)in_sizes; (void)n_in; (void)out_size;
    const float* x    = (const float*)d_in[0];
    const float* Wih0 = (const float*)d_in[1];
    /* d_in[2] = Whh0: unused (h=0) */
    const float* bih0 = (const float*)d_in[3];
    const float* bhh0 = (const float*)d_in[4];
    const float* Wih1 = (const float*)d_in[5];
    /* d_in[6] = Whh1: unused (h=0) */
    const float* bih1 = (const float*)d_in[7];
    const float* bhh1 = (const float*)d_in[8];
    const float* Wp   = (const float*)d_in[9];
    const float* bp   = (const float*)d_in[10];
    const float* Wv   = (const float*)d_in[11];
    const float* bv   = (const float*)d_in[12];
    float* out = (float*)d_out;

    size_t shmem = (size_t)(TILE_B * XS_STRIDE + TILE_B * H0_STRIDE) * sizeof(float); // 100 KB
    cudaFuncSetAttribute(lstm_policy_fused,
                         cudaFuncAttributeMaxDynamicSharedMemorySize, (int)shmem);

    lstm_policy_fused<<<BATCH / TILE_B, THREADS, shmem>>>(
        x, Wih0, bih0, bhh0, Wih1, bih1, bhh1, Wp, bp, Wv, bv, out);
}